// round 14
// baseline (speedup 1.0000x reference)
#include <cuda_runtime.h>
#include <cuda_fp16.h>
#include <cstdint>

// ============================================================================
// Problem constants
// ============================================================================
#define B_DIM   8
#define L_DIM   4096
#define CH_IN   1024
#define CH_OUT  1024
#define WD      512
#define M_TOTAL (B_DIM * L_DIM)   // 32768

#define AFF_GAIN   0.04419417382415922f   // 1/sqrt(512)
#define LRELU_GAIN 1.4142135f
#define CLAMP_V    256.0f

// ============================================================================
// Scratch (device globals — no allocations allowed)
// ============================================================================
__device__ __half g_xm[(size_t)M_TOTAL * CH_IN];   // modulated x, fp16 (64 MB)
__device__ __half g_wb[(size_t)CH_OUT * CH_IN];    // weight, fp16 (2 MB)
__device__ float g_styles[B_DIM * CH_IN];
__device__ float g_dcoefs[B_DIM * CH_OUT];

// ============================================================================
// Helpers
// ============================================================================
__device__ __forceinline__ uint32_t smem_to_u32(const void* p) {
    uint32_t a;
    asm("{ .reg .u64 t; cvta.to.shared.u64 t, %1; cvt.u32.u64 %0, t; }" : "=r"(a) : "l"(p));
    return a;
}

// 128B-period XOR swizzle: chunk bits [4:6] ^= bits [7:9]
__device__ __forceinline__ uint32_t swz(uint32_t off) {
    return off ^ ((off >> 3) & 0x70);
}

__device__ __forceinline__ void cp_async16(uint32_t dst, const void* src) {
    asm volatile("cp.async.cg.shared.global [%0], [%1], 16;" :: "r"(dst), "l"(src));
}
__device__ __forceinline__ void cp_commit() {
    asm volatile("cp.async.commit_group;" ::: "memory");
}
__device__ __forceinline__ void cp_wait2() {
    asm volatile("cp.async.wait_group 2;" ::: "memory");
}

__device__ __forceinline__ void ldmatrix_x4(uint32_t* r, uint32_t addr) {
    asm volatile("ldmatrix.sync.aligned.m8n8.x4.shared.b16 {%0,%1,%2,%3}, [%4];"
        : "=r"(r[0]), "=r"(r[1]), "=r"(r[2]), "=r"(r[3]) : "r"(addr));
}

// fp16 MMA with f16 accumulators: C/D = 2 b32 regs (4 halves).
__device__ __forceinline__ void mma16816h(uint32_t* c, const uint32_t* a, const uint32_t* b) {
    asm volatile(
        "mma.sync.aligned.m16n8k16.row.col.f16.f16.f16.f16 "
        "{%0,%1}, {%2,%3,%4,%5}, {%6,%7}, {%0,%1};"
        : "+r"(c[0]), "+r"(c[1])
        : "r"(a[0]), "r"(a[1]), "r"(a[2]), "r"(a[3]), "r"(b[0]), "r"(b[1]));
}

__device__ __forceinline__ uint32_t pack_f16x2(float lo, float hi) {
    uint32_t r;
    asm("cvt.rn.f16x2.f32 %0, %1, %2;" : "=r"(r) : "f"(hi), "f"(lo));
    return r;
}

// ============================================================================
// Pass 1: styles[b,i] = sum_k w[b,k] * aff_w[i,k] * gain + aff_b[i]
// ============================================================================
__global__ __launch_bounds__(256) void styles_kernel(
    const float* __restrict__ w, const float* __restrict__ aff_w,
    const float* __restrict__ aff_b)
{
    int warp = blockIdx.x * 8 + (threadIdx.x >> 5);   // 0..8191
    int lid  = threadIdx.x & 31;
    int b = warp >> 10, i = warp & 1023;
    const float* ar = aff_w + (size_t)i * WD;
    const float* wr = w + b * WD;
    float s = 0.f;
#pragma unroll
    for (int j = 0; j < WD / 32; j++)
        s += ar[lid + 32 * j] * wr[lid + 32 * j];
#pragma unroll
    for (int o = 16; o; o >>= 1) s += __shfl_xor_sync(0xFFFFFFFFu, s, o);
    if (lid == 0) g_styles[b * CH_IN + i] = s * AFF_GAIN + aff_b[i];
}

// ============================================================================
// Pass 2 (fused): xconv (all 16384 blocks) + dcoefs & wconv (blocks 0..1023)
// ============================================================================
__global__ __launch_bounds__(256) void prep2_kernel(
    const float* __restrict__ x, const float* __restrict__ weight)
{
    // ---- xconv slice: 8 elems per thread ----
    size_t idx = ((size_t)blockIdx.x * 256 + threadIdx.x) * 8;
    {
        int c = (int)(idx & (CH_IN - 1));
        int b = (int)(idx >> 22);   // idx / (4096*1024)
        const float4* xp = (const float4*)(x + idx);
        const float4* sp = (const float4*)(g_styles + b * CH_IN + c);
        float4 x0 = xp[0], x1 = xp[1];
        float4 s0 = sp[0], s1 = sp[1];
        uint4 p;
        p.x = pack_f16x2(x0.x * s0.x, x0.y * s0.y);
        p.y = pack_f16x2(x0.z * s0.z, x0.w * s0.w);
        p.z = pack_f16x2(x1.x * s1.x, x1.y * s1.y);
        p.w = pack_f16x2(x1.z * s1.z, x1.w * s1.w);
        *(uint4*)(g_xm + idx) = p;
    }

    if (blockIdx.x < 1024) {
        // ---- dcoefs: one warp per (b,o) ----
        int warp = blockIdx.x * 8 + (threadIdx.x >> 5);
        int lid  = threadIdx.x & 31;
        int b = warp >> 10, o = warp & 1023;
        const float* wr = weight + (size_t)o * CH_IN;
        const float* sr = g_styles + b * CH_IN;
        float acc = 0.f;
#pragma unroll
        for (int j = 0; j < CH_IN / 32; j++) {
            float wv = wr[lid + 32 * j];
            float sv = sr[lid + 32 * j];
            acc += (wv * wv) * (sv * sv);
        }
#pragma unroll
        for (int o2 = 16; o2; o2 >>= 1) acc += __shfl_xor_sync(0xFFFFFFFFu, acc, o2);
        if (lid == 0) g_dcoefs[b * CH_OUT + o] = rsqrtf(acc + 1e-8f);

        // ---- wconv: 1024 elems per block (4 per thread) ----
        size_t wbase = ((size_t)blockIdx.x * 1024 + threadIdx.x * 4);
        float4 v = *(const float4*)(weight + wbase);
        uint2 p;
        p.x = pack_f16x2(v.x, v.y);
        p.y = pack_f16x2(v.z, v.w);
        *(uint2*)(g_wb + wbase) = p;
    }
}

// ============================================================================
// Pass 3: GEMM 32768x1024x1024 (fp16 mma.sync, f16 accum) + fused epilogue
//   R8 configuration (best measured): BM=BN=128, BK=32, 256 threads
//   (warps 4M x 2N, 32x64 each), 4 cp.async stages, interleaved per-k16 loads.
// ============================================================================
#define BK 32
#define KTILES (CH_IN / BK)        // 32
#define NSTAGE 4
#define STAGE_BYTES 16384          // A 8KB + B 8KB
#define SM_EPI 0                   // dc[128] bias[128] ls[128] = 1536B
#define SM_AB  2048
#define SM_TOTAL (SM_AB + NSTAGE * STAGE_BYTES)   // 67584

__global__ __launch_bounds__(256, 2) void gemm_kernel(
    const float* __restrict__ x, const float* __restrict__ bias,
    const float* __restrict__ ls, float* __restrict__ out)
{
    extern __shared__ char smem[];
    const uint32_t smem_u = smem_to_u32(smem);
    const int tid = threadIdx.x;
    const int wid = tid >> 5, lid = tid & 31;
    const int n0g = blockIdx.x * 128;
    const int m0g = blockIdx.y * 128;
    const int b   = m0g >> 12;            // tiles never straddle batch

    float* dc_s = (float*)(smem + SM_EPI);
    float* bi_s = (float*)(smem + SM_EPI + 512);
    float* ls_s = (float*)(smem + SM_EPI + 1024);
    if (tid < 128) {
        dc_s[tid] = g_dcoefs[b * CH_OUT + n0g + tid];
        bi_s[tid] = bias[n0g + tid];
        ls_s[tid] = ls[n0g + tid];
    }

    // ---- cp.async lane parameters ----
    const int r = tid >> 2, c = tid & 3;
    const uint32_t d0 = swz((uint32_t)(r * 64 + c * 16));
    const uint32_t d1 = swz((uint32_t)((r + 64) * 64 + c * 16));
    const __half* asrc0 = g_xm + (size_t)(m0g + r)      * CH_IN + c * 8;
    const __half* asrc1 = g_xm + (size_t)(m0g + 64 + r) * CH_IN + c * 8;
    const __half* bsrc0 = g_wb + (size_t)(n0g + r)      * CH_IN + c * 8;
    const __half* bsrc1 = g_wb + (size_t)(n0g + 64 + r) * CH_IN + c * 8;

    // ---- ldmatrix per-lane addresses ----
    const int wm = wid & 3;      // M warp (32 rows)
    const int wn = wid >> 2;     // N warp (64 cols)
    uint32_t aaddr[2][2];        // [k16][mi]
    uint32_t baddr[2][4];        // [k16][ntp]
#pragma unroll
    for (int k16 = 0; k16 < 2; k16++) {
#pragma unroll
        for (int mi = 0; mi < 2; mi++) {
            int row = wm * 32 + mi * 16 + (lid & 15);
            int ch  = k16 * 2 + (lid >> 4);
            aaddr[k16][mi] = smem_u + SM_AB + swz((uint32_t)(row * 64 + ch * 16));
        }
#pragma unroll
        for (int ntp = 0; ntp < 4; ntp++) {
            int row = wn * 64 + ntp * 16 + ((lid >> 4) * 8) + (lid & 7);
            int ch  = k16 * 2 + ((lid >> 3) & 1);
            baddr[k16][ntp] = smem_u + SM_AB + 8192 + swz((uint32_t)(row * 64 + ch * 16));
        }
    }

    // f16 accumulators: [mi][ni][rowgroup], each u32 = half2 (cols jn, jn+1)
    uint32_t hacc[2][8][2];
#pragma unroll
    for (int mi = 0; mi < 2; mi++)
#pragma unroll
        for (int ni = 0; ni < 8; ni++) {
            hacc[mi][ni][0] = 0u;
            hacc[mi][ni][1] = 0u;
        }

    // ---- prefetch stages 0..2 ----
#pragma unroll
    for (int s = 0; s < NSTAGE - 1; s++) {
        int k0 = s * BK;
        uint32_t sa = smem_u + SM_AB + s * STAGE_BYTES;
        uint32_t sb = sa + 8192;
        cp_async16(sa + d0, asrc0 + k0);
        cp_async16(sa + d1, asrc1 + k0);
        cp_async16(sb + d0, bsrc0 + k0);
        cp_async16(sb + d1, bsrc1 + k0);
        cp_commit();
    }

    // ---- main loop ----
    for (int kt = 0; kt < KTILES; kt++) {
        cp_wait2();
        __syncthreads();

        int kp = kt + (NSTAGE - 1);
        if (kp < KTILES) {
            int k0 = kp * BK;
            uint32_t sa = smem_u + SM_AB + (kp & (NSTAGE - 1)) * STAGE_BYTES;
            uint32_t sb = sa + 8192;
            cp_async16(sa + d0, asrc0 + k0);
            cp_async16(sa + d1, asrc1 + k0);
            cp_async16(sb + d0, bsrc0 + k0);
            cp_async16(sb + d1, bsrc1 + k0);
        }
        cp_commit();

        const uint32_t soff = (uint32_t)(kt & (NSTAGE - 1)) * STAGE_BYTES;
#pragma unroll
        for (int k16 = 0; k16 < 2; k16++) {
            uint32_t a[2][4], bq[4][4];
            ldmatrix_x4(a[0], aaddr[k16][0] + soff);
            ldmatrix_x4(a[1], aaddr[k16][1] + soff);
#pragma unroll
            for (int ntp = 0; ntp < 4; ntp++)
                ldmatrix_x4(bq[ntp], baddr[k16][ntp] + soff);
#pragma unroll
            for (int mi = 0; mi < 2; mi++)
#pragma unroll
                for (int ni = 0; ni < 8; ni++)
                    mma16816h(hacc[mi][ni], a[mi], &bq[ni >> 1][(ni & 1) * 2]);
        }
    }

    // ---- fused epilogue: demod -> lrelu*sqrt2 -> clamp -> *layerscale + x ----
#pragma unroll
    for (int mi = 0; mi < 2; mi++) {
#pragma unroll
        for (int ni = 0; ni < 8; ni++) {
            int jn = wn * 64 + ni * 8 + (lid & 3) * 2;
            float dcv0 = dc_s[jn],     dcv1 = dc_s[jn + 1];
            float biv0 = bi_s[jn],     biv1 = bi_s[jn + 1];
            float lsv0 = ls_s[jn],     lsv1 = ls_s[jn + 1];
#pragma unroll
            for (int half = 0; half < 2; half++) {
                int m = m0g + wm * 32 + mi * 16 + (lid >> 2) + half * 8;
                const float2* xp = (const float2*)(x + (size_t)m * CH_OUT + n0g + jn);
                float2* op = (float2*)(out + (size_t)m * CH_OUT + n0g + jn);
                float2 xv = *xp;
                __half2 hv = *(__half2*)&hacc[mi][ni][half];
                float v0 = __low2float(hv)  * dcv0 + biv0;
                float v1 = __high2float(hv) * dcv1 + biv1;
                v0 = (v0 < 0.f) ? 0.2f * v0 : v0;
                v1 = (v1 < 0.f) ? 0.2f * v1 : v1;
                v0 *= LRELU_GAIN; v1 *= LRELU_GAIN;
                v0 = fminf(fmaxf(v0, -CLAMP_V), CLAMP_V);
                v1 = fminf(fmaxf(v1, -CLAMP_V), CLAMP_V);
                float2 ov;
                ov.x = v0 * lsv0 + xv.x;
                ov.y = v1 * lsv1 + xv.y;
                *op = ov;
            }
        }
    }
}

// ============================================================================
// Launch
// ============================================================================
extern "C" void kernel_launch(void* const* d_in, const int* in_sizes, int n_in,
                              void* d_out, int out_size)
{
    const float* x      = (const float*)d_in[0];   // (8, 4096, 1024)
    const float* w      = (const float*)d_in[1];   // (8, 512)
    const float* weight = (const float*)d_in[2];   // (1024, 1024)
    const float* bias   = (const float*)d_in[3];   // (1024,)
    const float* aff_w  = (const float*)d_in[4];   // (1024, 512)
    const float* aff_b  = (const float*)d_in[5];   // (1024,)
    const float* lsc    = (const float*)d_in[6];   // (1, 1, 1024)
    float* out = (float*)d_out;

    cudaFuncSetAttribute(gemm_kernel, cudaFuncAttributeMaxDynamicSharedMemorySize, SM_TOTAL);

    styles_kernel<<<1024, 256>>>(w, aff_w, aff_b);
    prep2_kernel<<<16384, 256>>>(x, weight);
    gemm_kernel<<<dim3(CH_OUT / 128, M_TOTAL / 128), 256, SM_TOTAL>>>(x, bias, lsc, out);
}

// round 15
// speedup vs baseline: 1.5795x; 1.5795x over previous
#include <cuda_runtime.h>
#include <cuda_bf16.h>
#include <cstdint>

// ============================================================================
// Problem constants
// ============================================================================
#define B_DIM   8
#define L_DIM   4096
#define CH_IN   1024
#define CH_OUT  1024
#define WD      512
#define M_TOTAL (B_DIM * L_DIM)   // 32768

#define AFF_GAIN   0.04419417382415922f   // 1/sqrt(512)
#define LRELU_GAIN 1.4142135f
#define CLAMP_V    256.0f

// ============================================================================
// Scratch (device globals — no allocations allowed)
// ============================================================================
__device__ __nv_bfloat16 g_xm[(size_t)M_TOTAL * CH_IN];   // modulated x, bf16 (64 MB)
__device__ __nv_bfloat16 g_wb[(size_t)CH_OUT * CH_IN];    // weight, bf16 (2 MB)
__device__ float g_styles[B_DIM * CH_IN];
__device__ float g_dcoefs[B_DIM * CH_OUT];

// ============================================================================
// Helpers
// ============================================================================
__device__ __forceinline__ uint32_t smem_to_u32(const void* p) {
    uint32_t a;
    asm("{ .reg .u64 t; cvta.to.shared.u64 t, %1; cvt.u32.u64 %0, t; }" : "=r"(a) : "l"(p));
    return a;
}

// 128B-period XOR swizzle: chunk bits [4:6] ^= bits [7:9]
__device__ __forceinline__ uint32_t swz(uint32_t off) {
    return off ^ ((off >> 3) & 0x70);
}

__device__ __forceinline__ void cp_async16(uint32_t dst, const void* src) {
    asm volatile("cp.async.cg.shared.global [%0], [%1], 16;" :: "r"(dst), "l"(src));
}
__device__ __forceinline__ void cp_commit() {
    asm volatile("cp.async.commit_group;" ::: "memory");
}
__device__ __forceinline__ void cp_wait2() {
    asm volatile("cp.async.wait_group 2;" ::: "memory");
}

__device__ __forceinline__ void ldmatrix_x4(uint32_t* r, uint32_t addr) {
    asm volatile("ldmatrix.sync.aligned.m8n8.x4.shared.b16 {%0,%1,%2,%3}, [%4];"
        : "=r"(r[0]), "=r"(r[1]), "=r"(r[2]), "=r"(r[3]) : "r"(addr));
}

__device__ __forceinline__ void mma16816(float* c, const uint32_t* a, const uint32_t* b) {
    asm volatile(
        "mma.sync.aligned.m16n8k16.row.col.f32.bf16.bf16.f32 "
        "{%0,%1,%2,%3}, {%4,%5,%6,%7}, {%8,%9}, {%0,%1,%2,%3};"
        : "+f"(c[0]), "+f"(c[1]), "+f"(c[2]), "+f"(c[3])
        : "r"(a[0]), "r"(a[1]), "r"(a[2]), "r"(a[3]), "r"(b[0]), "r"(b[1]));
}

__device__ __forceinline__ uint32_t pack_bf16x2(float lo, float hi) {
    uint32_t r;
    asm("cvt.rn.bf16x2.f32 %0, %1, %2;" : "=r"(r) : "f"(hi), "f"(lo));
    return r;
}

// ============================================================================
// Pass 1: styles[b,i] = sum_k w[b,k] * aff_w[i,k] * gain + aff_b[i]
// ============================================================================
__global__ __launch_bounds__(256) void styles_kernel(
    const float* __restrict__ w, const float* __restrict__ aff_w,
    const float* __restrict__ aff_b)
{
    int warp = blockIdx.x * 8 + (threadIdx.x >> 5);   // 0..8191
    int lid  = threadIdx.x & 31;
    int b = warp >> 10, i = warp & 1023;
    const float* ar = aff_w + (size_t)i * WD;
    const float* wr = w + b * WD;
    float s = 0.f;
#pragma unroll
    for (int j = 0; j < WD / 32; j++)
        s += ar[lid + 32 * j] * wr[lid + 32 * j];
#pragma unroll
    for (int o = 16; o; o >>= 1) s += __shfl_xor_sync(0xFFFFFFFFu, s, o);
    if (lid == 0) g_styles[b * CH_IN + i] = s * AFF_GAIN + aff_b[i];
}

// ============================================================================
// Pass 2 (fused): xconv (all blocks) + dcoefs & wconv (blocks 0..1023)
// ============================================================================
__global__ __launch_bounds__(256) void prep2_kernel(
    const float* __restrict__ x, const float* __restrict__ weight)
{
    // ---- xconv slice: 8 elems per thread ----
    size_t idx = ((size_t)blockIdx.x * 256 + threadIdx.x) * 8;
    {
        int c = (int)(idx & (CH_IN - 1));
        int b = (int)(idx >> 22);   // idx / (4096*1024)
        const float4* xp = (const float4*)(x + idx);
        const float4* sp = (const float4*)(g_styles + b * CH_IN + c);
        float4 x0 = xp[0], x1 = xp[1];
        float4 s0 = sp[0], s1 = sp[1];
        uint4 p;
        p.x = pack_bf16x2(x0.x * s0.x, x0.y * s0.y);
        p.y = pack_bf16x2(x0.z * s0.z, x0.w * s0.w);
        p.z = pack_bf16x2(x1.x * s1.x, x1.y * s1.y);
        p.w = pack_bf16x2(x1.z * s1.z, x1.w * s1.w);
        *(uint4*)(g_xm + idx) = p;
    }

    if (blockIdx.x < 1024) {
        // ---- dcoefs: one warp per (b,o) ----
        int warp = blockIdx.x * 8 + (threadIdx.x >> 5);
        int lid  = threadIdx.x & 31;
        int b = warp >> 10, o = warp & 1023;
        const float* wr = weight + (size_t)o * CH_IN;
        const float* sr = g_styles + b * CH_IN;
        float acc = 0.f;
#pragma unroll
        for (int j = 0; j < CH_IN / 32; j++) {
            float wv = wr[lid + 32 * j];
            float sv = sr[lid + 32 * j];
            acc += (wv * wv) * (sv * sv);
        }
#pragma unroll
        for (int o2 = 16; o2; o2 >>= 1) acc += __shfl_xor_sync(0xFFFFFFFFu, acc, o2);
        if (lid == 0) g_dcoefs[b * CH_OUT + o] = rsqrtf(acc + 1e-8f);

        // ---- wconv: 1024 elems per block (4 per thread) ----
        size_t wbase = ((size_t)blockIdx.x * 1024 + threadIdx.x * 4);
        float4 v = *(const float4*)(weight + wbase);
        uint2 p;
        p.x = pack_bf16x2(v.x, v.y);
        p.y = pack_bf16x2(v.z, v.w);
        *(uint2*)(g_wb + wbase) = p;
    }
}

// ============================================================================
// Dummy kernel: phase-shifter so the ncu-profiled launch (#3) is the gemm.
// ============================================================================
__global__ void dummy_kernel() {}

// ============================================================================
// Pass 3: GEMM 32768x1024x1024 (bf16 mma.sync) + fused epilogue
//   Best-measured configuration (R8, 219.8us): BM=BN=128, BK=32, 256 threads
//   (warps 4M x 2N, 32x64 each), 4 cp.async stages.
// ============================================================================
#define BK 32
#define KTILES (CH_IN / BK)        // 32
#define NSTAGE 4
#define STAGE_BYTES 16384          // A 8KB + B 8KB
#define SM_EPI 0                   // dc[128] bias[128] ls[128] = 1536B
#define SM_AB  2048
#define SM_TOTAL (SM_AB + NSTAGE * STAGE_BYTES)   // 67584

__global__ __launch_bounds__(256, 2) void gemm_kernel(
    const float* __restrict__ x, const float* __restrict__ bias,
    const float* __restrict__ ls, float* __restrict__ out)
{
    extern __shared__ char smem[];
    const uint32_t smem_u = smem_to_u32(smem);
    const int tid = threadIdx.x;
    const int wid = tid >> 5, lid = tid & 31;
    const int n0g = blockIdx.x * 128;
    const int m0g = blockIdx.y * 128;
    const int b   = m0g >> 12;            // tiles never straddle batch

    float* dc_s = (float*)(smem + SM_EPI);
    float* bi_s = (float*)(smem + SM_EPI + 512);
    float* ls_s = (float*)(smem + SM_EPI + 1024);
    if (tid < 128) {
        dc_s[tid] = g_dcoefs[b * CH_OUT + n0g + tid];
        bi_s[tid] = bias[n0g + tid];
        ls_s[tid] = ls[n0g + tid];
    }

    // ---- cp.async lane parameters ----
    const int r = tid >> 2, c = tid & 3;
    const uint32_t d0 = swz((uint32_t)(r * 64 + c * 16));
    const uint32_t d1 = swz((uint32_t)((r + 64) * 64 + c * 16));
    const __nv_bfloat16* asrc0 = g_xm + (size_t)(m0g + r)      * CH_IN + c * 8;
    const __nv_bfloat16* asrc1 = g_xm + (size_t)(m0g + 64 + r) * CH_IN + c * 8;
    const __nv_bfloat16* bsrc0 = g_wb + (size_t)(n0g + r)      * CH_IN + c * 8;
    const __nv_bfloat16* bsrc1 = g_wb + (size_t)(n0g + 64 + r) * CH_IN + c * 8;

    // ---- ldmatrix per-lane addresses ----
    const int wm = wid & 3;      // M warp (32 rows)
    const int wn = wid >> 2;     // N warp (64 cols)
    uint32_t aaddr[2][2];        // [k16][mi]
    uint32_t baddr[2][4];        // [k16][ntp]
#pragma unroll
    for (int k16 = 0; k16 < 2; k16++) {
#pragma unroll
        for (int mi = 0; mi < 2; mi++) {
            int row = wm * 32 + mi * 16 + (lid & 15);
            int ch  = k16 * 2 + (lid >> 4);
            aaddr[k16][mi] = smem_u + SM_AB + swz((uint32_t)(row * 64 + ch * 16));
        }
#pragma unroll
        for (int ntp = 0; ntp < 4; ntp++) {
            int row = wn * 64 + ntp * 16 + ((lid >> 4) * 8) + (lid & 7);
            int ch  = k16 * 2 + ((lid >> 3) & 1);
            baddr[k16][ntp] = smem_u + SM_AB + 8192 + swz((uint32_t)(row * 64 + ch * 16));
        }
    }

    float acc[2][8][4];
#pragma unroll
    for (int mi = 0; mi < 2; mi++)
#pragma unroll
        for (int ni = 0; ni < 8; ni++)
#pragma unroll
            for (int e = 0; e < 4; e++) acc[mi][ni][e] = 0.f;

    // ---- prefetch stages 0..2 ----
#pragma unroll
    for (int s = 0; s < NSTAGE - 1; s++) {
        int k0 = s * BK;
        uint32_t sa = smem_u + SM_AB + s * STAGE_BYTES;
        uint32_t sb = sa + 8192;
        cp_async16(sa + d0, asrc0 + k0);
        cp_async16(sa + d1, asrc1 + k0);
        cp_async16(sb + d0, bsrc0 + k0);
        cp_async16(sb + d1, bsrc1 + k0);
        cp_commit();
    }

    // ---- main loop ----
    for (int kt = 0; kt < KTILES; kt++) {
        cp_wait2();
        __syncthreads();

        int kp = kt + (NSTAGE - 1);
        if (kp < KTILES) {
            int k0 = kp * BK;
            uint32_t sa = smem_u + SM_AB + (kp & (NSTAGE - 1)) * STAGE_BYTES;
            uint32_t sb = sa + 8192;
            cp_async16(sa + d0, asrc0 + k0);
            cp_async16(sa + d1, asrc1 + k0);
            cp_async16(sb + d0, bsrc0 + k0);
            cp_async16(sb + d1, bsrc1 + k0);
        }
        cp_commit();

        const uint32_t soff = (uint32_t)(kt & (NSTAGE - 1)) * STAGE_BYTES;
#pragma unroll
        for (int k16 = 0; k16 < 2; k16++) {
            uint32_t a[2][4], bq[4][4];
            ldmatrix_x4(a[0], aaddr[k16][0] + soff);
            ldmatrix_x4(a[1], aaddr[k16][1] + soff);
#pragma unroll
            for (int ntp = 0; ntp < 4; ntp++)
                ldmatrix_x4(bq[ntp], baddr[k16][ntp] + soff);
#pragma unroll
            for (int mi = 0; mi < 2; mi++)
#pragma unroll
                for (int ni = 0; ni < 8; ni++)
                    mma16816(acc[mi][ni], a[mi], &bq[ni >> 1][(ni & 1) * 2]);
        }
    }

    // ---- fused epilogue: demod -> lrelu*sqrt2 -> clamp -> *layerscale + x ----
#pragma unroll
    for (int mi = 0; mi < 2; mi++) {
#pragma unroll
        for (int ni = 0; ni < 8; ni++) {
            int jn = wn * 64 + ni * 8 + (lid & 3) * 2;
            float dcv0 = dc_s[jn],     dcv1 = dc_s[jn + 1];
            float biv0 = bi_s[jn],     biv1 = bi_s[jn + 1];
            float lsv0 = ls_s[jn],     lsv1 = ls_s[jn + 1];
#pragma unroll
            for (int half = 0; half < 2; half++) {
                int m = m0g + wm * 32 + mi * 16 + (lid >> 2) + half * 8;
                const float2* xp = (const float2*)(x + (size_t)m * CH_OUT + n0g + jn);
                float2* op = (float2*)(out + (size_t)m * CH_OUT + n0g + jn);
                float2 xv = *xp;
                float v0 = acc[mi][ni][half * 2 + 0] * dcv0 + biv0;
                float v1 = acc[mi][ni][half * 2 + 1] * dcv1 + biv1;
                v0 = (v0 < 0.f) ? 0.2f * v0 : v0;
                v1 = (v1 < 0.f) ? 0.2f * v1 : v1;
                v0 *= LRELU_GAIN; v1 *= LRELU_GAIN;
                v0 = fminf(fmaxf(v0, -CLAMP_V), CLAMP_V);
                v1 = fminf(fmaxf(v1, -CLAMP_V), CLAMP_V);
                float2 ov;
                ov.x = v0 * lsv0 + xv.x;
                ov.y = v1 * lsv1 + xv.y;
                *op = ov;
            }
        }
    }
}

// ============================================================================
// Launch: styles(0), prep2(1), dummy(2), gemm(3) — ncu profiles launch #3.
// ============================================================================
extern "C" void kernel_launch(void* const* d_in, const int* in_sizes, int n_in,
                              void* d_out, int out_size)
{
    const float* x      = (const float*)d_in[0];   // (8, 4096, 1024)
    const float* w      = (const float*)d_in[1];   // (8, 512)
    const float* weight = (const float*)d_in[2];   // (1024, 1024)
    const float* bias   = (const float*)d_in[3];   // (1024,)
    const float* aff_w  = (const float*)d_in[4];   // (1024, 512)
    const float* aff_b  = (const float*)d_in[5];   // (1024,)
    const float* lsc    = (const float*)d_in[6];   // (1, 1, 1024)
    float* out = (float*)d_out;

    cudaFuncSetAttribute(gemm_kernel, cudaFuncAttributeMaxDynamicSharedMemorySize, SM_TOTAL);

    styles_kernel<<<1024, 256>>>(w, aff_w, aff_b);
    prep2_kernel<<<16384, 256>>>(x, weight);
    dummy_kernel<<<1, 32>>>();
    gemm_kernel<<<dim3(CH_OUT / 128, M_TOTAL / 128), 256, SM_TOTAL>>>(x, bias, lsc, out);
}

// round 16
// speedup vs baseline: 1.5809x; 1.0009x over previous
#include <cuda_runtime.h>
#include <cuda_bf16.h>
#include <cstdint>

// ============================================================================
// Problem constants
// ============================================================================
#define B_DIM   8
#define L_DIM   4096
#define CH_IN   1024
#define CH_OUT  1024
#define WD      512
#define M_TOTAL (B_DIM * L_DIM)   // 32768

#define AFF_GAIN   0.04419417382415922f   // 1/sqrt(512)
#define LRELU_GAIN 1.4142135f
#define CLAMP_V    256.0f

// ============================================================================
// Scratch (device globals — no allocations allowed)
// ============================================================================
__device__ __nv_bfloat16 g_xm[(size_t)M_TOTAL * CH_IN];   // modulated x, bf16 (64 MB)
__device__ __nv_bfloat16 g_wb[(size_t)CH_OUT * CH_IN];    // weight, bf16 (2 MB)
__device__ float g_styles[B_DIM * CH_IN];
__device__ float g_dcoefs[B_DIM * CH_OUT];

// ============================================================================
// Helpers
// ============================================================================
__device__ __forceinline__ uint32_t smem_to_u32(const void* p) {
    uint32_t a;
    asm("{ .reg .u64 t; cvta.to.shared.u64 t, %1; cvt.u32.u64 %0, t; }" : "=r"(a) : "l"(p));
    return a;
}

// 128B-period XOR swizzle: chunk bits [4:6] ^= bits [7:9]
__device__ __forceinline__ uint32_t swz(uint32_t off) {
    return off ^ ((off >> 3) & 0x70);
}

__device__ __forceinline__ void cp_async16(uint32_t dst, const void* src) {
    asm volatile("cp.async.cg.shared.global [%0], [%1], 16;" :: "r"(dst), "l"(src));
}
__device__ __forceinline__ void cp_commit() {
    asm volatile("cp.async.commit_group;" ::: "memory");
}
__device__ __forceinline__ void cp_wait2() {
    asm volatile("cp.async.wait_group 2;" ::: "memory");
}

__device__ __forceinline__ void ldmatrix_x4(uint32_t* r, uint32_t addr) {
    asm volatile("ldmatrix.sync.aligned.m8n8.x4.shared.b16 {%0,%1,%2,%3}, [%4];"
        : "=r"(r[0]), "=r"(r[1]), "=r"(r[2]), "=r"(r[3]) : "r"(addr));
}

__device__ __forceinline__ void mma16816(float* c, const uint32_t* a, const uint32_t* b) {
    asm volatile(
        "mma.sync.aligned.m16n8k16.row.col.f32.bf16.bf16.f32 "
        "{%0,%1,%2,%3}, {%4,%5,%6,%7}, {%8,%9}, {%0,%1,%2,%3};"
        : "+f"(c[0]), "+f"(c[1]), "+f"(c[2]), "+f"(c[3])
        : "r"(a[0]), "r"(a[1]), "r"(a[2]), "r"(a[3]), "r"(b[0]), "r"(b[1]));
}

__device__ __forceinline__ uint32_t pack_bf16x2(float lo, float hi) {
    uint32_t r;
    asm("cvt.rn.bf16x2.f32 %0, %1, %2;" : "=r"(r) : "f"(hi), "f"(lo));
    return r;
}

// ============================================================================
// Pass 1: styles[b,i] = sum_k w[b,k] * aff_w[i,k] * gain + aff_b[i]
//   One warp per TWO (b,i) outputs (better ILP per warp, half the grid).
// ============================================================================
__global__ __launch_bounds__(256) void styles_kernel(
    const float* __restrict__ w, const float* __restrict__ aff_w,
    const float* __restrict__ aff_b)
{
    int warp = blockIdx.x * 8 + (threadIdx.x >> 5);   // 0..4095
    int lid  = threadIdx.x & 31;
    int o0 = warp * 2;                                 // output pair
    int b0 = o0 >> 10, i0 = o0 & 1023;
    int b1 = (o0 + 1) >> 10, i1 = (o0 + 1) & 1023;
    const float* ar0 = aff_w + (size_t)i0 * WD;
    const float* ar1 = aff_w + (size_t)i1 * WD;
    const float* wr0 = w + b0 * WD;
    const float* wr1 = w + b1 * WD;
    float s0 = 0.f, s1 = 0.f;
#pragma unroll
    for (int j = 0; j < WD / 32; j++) {
        s0 += ar0[lid + 32 * j] * wr0[lid + 32 * j];
        s1 += ar1[lid + 32 * j] * wr1[lid + 32 * j];
    }
#pragma unroll
    for (int o = 16; o; o >>= 1) {
        s0 += __shfl_xor_sync(0xFFFFFFFFu, s0, o);
        s1 += __shfl_xor_sync(0xFFFFFFFFu, s1, o);
    }
    if (lid == 0) {
        g_styles[b0 * CH_IN + i0] = s0 * AFF_GAIN + aff_b[i0];
        g_styles[b1 * CH_IN + i1] = s1 * AFF_GAIN + aff_b[i1];
    }
}

// ============================================================================
// Pass 2 (fused): xconv (all blocks) + dcoefs & wconv (blocks 0..1023)
// ============================================================================
__global__ __launch_bounds__(256) void prep2_kernel(
    const float* __restrict__ x, const float* __restrict__ weight)
{
    // ---- xconv slice: 8 elems per thread ----
    size_t idx = ((size_t)blockIdx.x * 256 + threadIdx.x) * 8;
    {
        int c = (int)(idx & (CH_IN - 1));
        int b = (int)(idx >> 22);   // idx / (4096*1024)
        const float4* xp = (const float4*)(x + idx);
        const float4* sp = (const float4*)(g_styles + b * CH_IN + c);
        float4 x0 = xp[0], x1 = xp[1];
        float4 s0 = sp[0], s1 = sp[1];
        uint4 p;
        p.x = pack_bf16x2(x0.x * s0.x, x0.y * s0.y);
        p.y = pack_bf16x2(x0.z * s0.z, x0.w * s0.w);
        p.z = pack_bf16x2(x1.x * s1.x, x1.y * s1.y);
        p.w = pack_bf16x2(x1.z * s1.z, x1.w * s1.w);
        *(uint4*)(g_xm + idx) = p;
    }

    if (blockIdx.x < 1024) {
        // ---- dcoefs: one warp per (b,o) ----
        int warp = blockIdx.x * 8 + (threadIdx.x >> 5);
        int lid  = threadIdx.x & 31;
        int b = warp >> 10, o = warp & 1023;
        const float* wr = weight + (size_t)o * CH_IN;
        const float* sr = g_styles + b * CH_IN;
        float acc = 0.f;
#pragma unroll
        for (int j = 0; j < CH_IN / 32; j++) {
            float wv = wr[lid + 32 * j];
            float sv = sr[lid + 32 * j];
            acc += (wv * wv) * (sv * sv);
        }
#pragma unroll
        for (int o2 = 16; o2; o2 >>= 1) acc += __shfl_xor_sync(0xFFFFFFFFu, acc, o2);
        if (lid == 0) g_dcoefs[b * CH_OUT + o] = rsqrtf(acc + 1e-8f);

        // ---- wconv: 1024 elems per block (4 per thread) ----
        size_t wbase = ((size_t)blockIdx.x * 1024 + threadIdx.x * 4);
        float4 v = *(const float4*)(weight + wbase);
        uint2 p;
        p.x = pack_bf16x2(v.x, v.y);
        p.y = pack_bf16x2(v.z, v.w);
        *(uint2*)(g_wb + wbase) = p;
    }
}

// ============================================================================
// Pass 3: GEMM 32768x1024x1024 (bf16 mma.sync) + fused epilogue
//   Best-measured configuration (R8/R15, 219.6us): BM=BN=128, BK=32,
//   256 threads (warps 4M x 2N, 32x64 each), 4 cp.async stages.
// ============================================================================
#define BK 32
#define KTILES (CH_IN / BK)        // 32
#define NSTAGE 4
#define STAGE_BYTES 16384          // A 8KB + B 8KB
#define SM_EPI 0                   // dc[128] bias[128] ls[128] = 1536B
#define SM_AB  2048
#define SM_TOTAL (SM_AB + NSTAGE * STAGE_BYTES)   // 67584

__global__ __launch_bounds__(256, 2) void gemm_kernel(
    const float* __restrict__ x, const float* __restrict__ bias,
    const float* __restrict__ ls, float* __restrict__ out)
{
    extern __shared__ char smem[];
    const uint32_t smem_u = smem_to_u32(smem);
    const int tid = threadIdx.x;
    const int wid = tid >> 5, lid = tid & 31;
    const int n0g = blockIdx.x * 128;
    const int m0g = blockIdx.y * 128;
    const int b   = m0g >> 12;            // tiles never straddle batch

    float* dc_s = (float*)(smem + SM_EPI);
    float* bi_s = (float*)(smem + SM_EPI + 512);
    float* ls_s = (float*)(smem + SM_EPI + 1024);
    if (tid < 128) {
        dc_s[tid] = g_dcoefs[b * CH_OUT + n0g + tid];
        bi_s[tid] = bias[n0g + tid];
        ls_s[tid] = ls[n0g + tid];
    }

    // ---- cp.async lane parameters ----
    const int r = tid >> 2, c = tid & 3;
    const uint32_t d0 = swz((uint32_t)(r * 64 + c * 16));
    const uint32_t d1 = swz((uint32_t)((r + 64) * 64 + c * 16));
    const __nv_bfloat16* asrc0 = g_xm + (size_t)(m0g + r)      * CH_IN + c * 8;
    const __nv_bfloat16* asrc1 = g_xm + (size_t)(m0g + 64 + r) * CH_IN + c * 8;
    const __nv_bfloat16* bsrc0 = g_wb + (size_t)(n0g + r)      * CH_IN + c * 8;
    const __nv_bfloat16* bsrc1 = g_wb + (size_t)(n0g + 64 + r) * CH_IN + c * 8;

    // ---- ldmatrix per-lane addresses ----
    const int wm = wid & 3;      // M warp (32 rows)
    const int wn = wid >> 2;     // N warp (64 cols)
    uint32_t aaddr[2][2];        // [k16][mi]
    uint32_t baddr[2][4];        // [k16][ntp]
#pragma unroll
    for (int k16 = 0; k16 < 2; k16++) {
#pragma unroll
        for (int mi = 0; mi < 2; mi++) {
            int row = wm * 32 + mi * 16 + (lid & 15);
            int ch  = k16 * 2 + (lid >> 4);
            aaddr[k16][mi] = smem_u + SM_AB + swz((uint32_t)(row * 64 + ch * 16));
        }
#pragma unroll
        for (int ntp = 0; ntp < 4; ntp++) {
            int row = wn * 64 + ntp * 16 + ((lid >> 4) * 8) + (lid & 7);
            int ch  = k16 * 2 + ((lid >> 3) & 1);
            baddr[k16][ntp] = smem_u + SM_AB + 8192 + swz((uint32_t)(row * 64 + ch * 16));
        }
    }

    float acc[2][8][4];
#pragma unroll
    for (int mi = 0; mi < 2; mi++)
#pragma unroll
        for (int ni = 0; ni < 8; ni++)
#pragma unroll
            for (int e = 0; e < 4; e++) acc[mi][ni][e] = 0.f;

    // ---- prefetch stages 0..2 ----
#pragma unroll
    for (int s = 0; s < NSTAGE - 1; s++) {
        int k0 = s * BK;
        uint32_t sa = smem_u + SM_AB + s * STAGE_BYTES;
        uint32_t sb = sa + 8192;
        cp_async16(sa + d0, asrc0 + k0);
        cp_async16(sa + d1, asrc1 + k0);
        cp_async16(sb + d0, bsrc0 + k0);
        cp_async16(sb + d1, bsrc1 + k0);
        cp_commit();
    }

    // ---- main loop ----
    for (int kt = 0; kt < KTILES; kt++) {
        cp_wait2();
        __syncthreads();

        int kp = kt + (NSTAGE - 1);
        if (kp < KTILES) {
            int k0 = kp * BK;
            uint32_t sa = smem_u + SM_AB + (kp & (NSTAGE - 1)) * STAGE_BYTES;
            uint32_t sb = sa + 8192;
            cp_async16(sa + d0, asrc0 + k0);
            cp_async16(sa + d1, asrc1 + k0);
            cp_async16(sb + d0, bsrc0 + k0);
            cp_async16(sb + d1, bsrc1 + k0);
        }
        cp_commit();

        const uint32_t soff = (uint32_t)(kt & (NSTAGE - 1)) * STAGE_BYTES;
#pragma unroll
        for (int k16 = 0; k16 < 2; k16++) {
            uint32_t a[2][4], bq[4][4];
            ldmatrix_x4(a[0], aaddr[k16][0] + soff);
            ldmatrix_x4(a[1], aaddr[k16][1] + soff);
#pragma unroll
            for (int ntp = 0; ntp < 4; ntp++)
                ldmatrix_x4(bq[ntp], baddr[k16][ntp] + soff);
#pragma unroll
            for (int mi = 0; mi < 2; mi++)
#pragma unroll
                for (int ni = 0; ni < 8; ni++)
                    mma16816(acc[mi][ni], a[mi], &bq[ni >> 1][(ni & 1) * 2]);
        }
    }

    // ---- fused epilogue: demod -> lrelu*sqrt2 -> clamp -> *layerscale + x ----
#pragma unroll
    for (int mi = 0; mi < 2; mi++) {
#pragma unroll
        for (int ni = 0; ni < 8; ni++) {
            int jn = wn * 64 + ni * 8 + (lid & 3) * 2;
            float dcv0 = dc_s[jn],     dcv1 = dc_s[jn + 1];
            float biv0 = bi_s[jn],     biv1 = bi_s[jn + 1];
            float lsv0 = ls_s[jn],     lsv1 = ls_s[jn + 1];
#pragma unroll
            for (int half = 0; half < 2; half++) {
                int m = m0g + wm * 32 + mi * 16 + (lid >> 2) + half * 8;
                const float2* xp = (const float2*)(x + (size_t)m * CH_OUT + n0g + jn);
                float2* op = (float2*)(out + (size_t)m * CH_OUT + n0g + jn);
                float2 xv = *xp;
                float v0 = acc[mi][ni][half * 2 + 0] * dcv0 + biv0;
                float v1 = acc[mi][ni][half * 2 + 1] * dcv1 + biv1;
                v0 = (v0 < 0.f) ? 0.2f * v0 : v0;
                v1 = (v1 < 0.f) ? 0.2f * v1 : v1;
                v0 *= LRELU_GAIN; v1 *= LRELU_GAIN;
                v0 = fminf(fmaxf(v0, -CLAMP_V), CLAMP_V);
                v1 = fminf(fmaxf(v1, -CLAMP_V), CLAMP_V);
                float2 ov;
                ov.x = v0 * lsv0 + xv.x;
                ov.y = v1 * lsv1 + xv.y;
                *op = ov;
            }
        }
    }
}

// ============================================================================
// Launch
// ============================================================================
extern "C" void kernel_launch(void* const* d_in, const int* in_sizes, int n_in,
                              void* d_out, int out_size)
{
    const float* x      = (const float*)d_in[0];   // (8, 4096, 1024)
    const float* w      = (const float*)d_in[1];   // (8, 512)
    const float* weight = (const float*)d_in[2];   // (1024, 1024)
    const float* bias   = (const float*)d_in[3];   // (1024,)
    const float* aff_w  = (const float*)d_in[4];   // (1024, 512)
    const float* aff_b  = (const float*)d_in[5];   // (1024,)
    const float* lsc    = (const float*)d_in[6];   // (1, 1, 1024)
    float* out = (float*)d_out;

    cudaFuncSetAttribute(gemm_kernel, cudaFuncAttributeMaxDynamicSharedMemorySize, SM_TOTAL);

    styles_kernel<<<512, 256>>>(w, aff_w, aff_b);     // one warp per 2 outputs
    prep2_kernel<<<16384, 256>>>(x, weight);
    gemm_kernel<<<dim3(CH_OUT / 128, M_TOTAL / 128), 256, SM_TOTAL>>>(x, bias, lsc, out);
}